// round 11
// baseline (speedup 1.0000x reference)
#include <cuda_runtime.h>

#define BATCH   4
#define NPTS    4096
#define TS      128
#define MICRO   8
#define TDIM    16
#define THREADS 256
#define NCGRP   (NPTS / TS)          // 32 col tiles (1 per block)
#define RTPB    4                    // row tiles per block
#define NRGRP   (NPTS / (TS * RTPB)) // 8 row groups
#define HALFK   (BATCH * NPTS)       // 16384
#define NKEY    (2 * HALFK)          // 32768 keys = 128 KB

// key = ~bits(d), d>=0: max(key)==min(d), zero is identity (no init kernel;
// reduce_kernel restores zeros + resets g_acc/g_cnt every launch).
__device__ unsigned g_key[NKEY];
__device__ float    g_acc;
__device__ unsigned g_cnt;

__device__ __forceinline__ float fsub1(float a, float b) {   // a-b, FFMA-imm
    float r;
    asm("fma.rn.f32 %0, %1, 0fBF800000, %2;" : "=f"(r) : "f"(b), "f"(a));
    return r;
}

// (u,v) = rst - cst via one packed fma.rn.f32x2
__device__ __forceinline__ void psub(unsigned long long cst,
                                     unsigned long long rst,
                                     unsigned long long neg1,
                                     float& u, float& v) {
    asm("{\n\t.reg .b64 t;\n\t"
        "fma.rn.f32x2 t, %2, %3, %4;\n\t"
        "mov.b64 {%0,%1}, t;\n\t}"
        : "=f"(u), "=f"(v) : "l"(cst), "l"(neg1), "l"(rst));
}

// 8 xyz points (24 contiguous floats, 16B aligned) -> named registers
__device__ __forceinline__ void load8pts(const float* __restrict__ p, int idx,
                                         float* x, float* y, float* z) {
    const float4* q = reinterpret_cast<const float4*>(p + idx * 3);
    const float4 a0 = q[0], a1 = q[1], a2 = q[2],
                 a3 = q[3], a4 = q[4], a5 = q[5];
    x[0] = a0.x; y[0] = a0.y; z[0] = a0.z;
    x[1] = a0.w; y[1] = a1.x; z[1] = a1.y;
    x[2] = a1.z; y[2] = a1.w; z[2] = a2.x;
    x[3] = a2.y; y[3] = a2.z; z[3] = a2.w;
    x[4] = a3.x; y[4] = a3.y; z[4] = a3.z;
    x[5] = a3.w; y[5] = a4.x; z[5] = a4.y;
    x[6] = a4.z; y[6] = a4.w; z[6] = a5.x;
    x[7] = a5.y; y[7] = a5.z; z[7] = a5.w;
}

__global__ __launch_bounds__(THREADS, 3)
void chamfer_main(const float* __restrict__ pred,
                  const float* __restrict__ gt) {
    const int tx   = threadIdx.x & (TDIM - 1);   // col subgroup
    const int ty   = threadIdx.x >> 4;           // row subgroup
    const int cgrp = blockIdx.x;                 // 0..31  (128 cols, fixed)
    const int rgrp = blockIdx.y;                 // 0..7   (4 row tiles)
    const int b    = blockIdx.z;

    // Row stage: 512 pred points as (s,t)=(x+y,x-y) + z, padded p+(p>>3).
    __shared__ float2 sst[576];
    __shared__ float  szs[576];
    __shared__ float  swcol[8][TS];              // col epilogue (used once)

    const float* prow = pred + (size_t)b * NPTS * 3;
    const float* pcol = gt   + (size_t)b * NPTS * 3;

    // Stage all 4 row tiles coalesced.
    const int rbase = rgrp * (TS * RTPB);        // 512-aligned
    #pragma unroll
    for (int k = 0; k < 2; k++) {
        const int p = threadIdx.x + k * 256;
        const float x = prow[(rbase + p) * 3 + 0];
        const float y = prow[(rbase + p) * 3 + 1];
        const float z = prow[(rbase + p) * 3 + 2];
        const int s = p + (p >> 3);
        sst[s] = make_float2(x + y, x - y);
        szs[s] = z;
    }

    // Col points live in registers for the whole block.
    const int c0 = cgrp * TS + tx * MICRO;
    float cxr[MICRO], cyr[MICRO], czr[MICRO];
    load8pts(pcol, c0, cxr, cyr, czr);
    unsigned long long cst[MICRO];
    float cz[MICRO], cmin[MICRO];
    #pragma unroll
    for (int j = 0; j < MICRO; j++) {
        const float s = cxr[j] + cyr[j], t = cxr[j] - cyr[j];
        asm("mov.b64 %0, {%1,%2};" : "=l"(cst[j]) : "f"(s), "f"(t));
        cz[j]  = czr[j];
        cmin[j] = 3.4e38f;
    }
    const unsigned long long NEG1 = 0xBF800000BF800000ULL;
    const int warp = threadIdx.x >> 5;
    const int lane = threadIdx.x & 31;
    __syncthreads();                             // stage ready (bar #1)

    #pragma unroll 1
    for (int t = 0; t < RTPB; t++) {
        // This thread's 8 rows: broadcast LDS (all tx lanes share addresses).
        const int pl = t * TS + ty * MICRO;      // local row index in stage
        unsigned long long rst[MICRO];
        float rz[MICRO], rmin[MICRO];
        #pragma unroll
        for (int i = 0; i < MICRO; i++) {
            const int s = (pl + i) + ((pl + i) >> 3);
            rst[i] = *reinterpret_cast<const unsigned long long*>(&sst[s]);
            rz[i]  = szs[s];
            rmin[i] = 3.4e38f;
        }

        // 64 pairs x 6 inst: FFMA2 + FFMA-imm + FMNMX(|u|,|v|) + FADD(+|dz|)
        // + 2 FMNMX.   (|dx|+|dy| = max(|dx+dy|,|dx-dy|))
        #pragma unroll
        for (int i = 0; i < MICRO; i++) {
            #pragma unroll
            for (int j = 0; j < MICRO; j++) {
                float u, v;
                psub(cst[j], rst[i], NEG1, u, v);
                const float dz = fsub1(rz[i], cz[j]);
                const float d  = fmaxf(fabsf(u), fabsf(v)) + fabsf(dz);
                rmin[i] = fminf(rmin[i], d);
                cmin[j] = fminf(cmin[j], d);
            }
        }

        // Row epilogue (shuffle-only, NO bars): fold across 16 tx lanes.
        #pragma unroll
        for (int i = 0; i < MICRO; i++) {
            #pragma unroll
            for (int o = 1; o < TDIM; o <<= 1)
                rmin[i] = fminf(rmin[i],
                                __shfl_xor_sync(0xffffffffu, rmin[i], o));
        }
        if (tx == 0) {
            #pragma unroll
            for (int i = 0; i < MICRO; i++)
                atomicMax(&g_key[b * NPTS + rbase + pl + i],
                          ~__float_as_uint(rmin[i]));
        }
    }

    // Col epilogue, ONCE: xor16 fold, lanes<16 STS, cross-warp min, REDG.MAX.
    #pragma unroll
    for (int j = 0; j < MICRO; j++)
        cmin[j] = fminf(cmin[j], __shfl_xor_sync(0xffffffffu, cmin[j], 16));
    if (lane < 16) {
        #pragma unroll
        for (int j = 0; j < MICRO; j++)
            swcol[warp][lane * MICRO + j] = cmin[j];
    }
    __syncthreads();                             // bar #2
    if (threadIdx.x < TS) {
        float m = swcol[0][threadIdx.x];
        #pragma unroll
        for (int w = 1; w < 8; w++)
            m = fminf(m, swcol[w][threadIdx.x]);
        atomicMax(&g_key[HALFK + b * NPTS + cgrp * TS + threadIdx.x],
                  ~__float_as_uint(m));
    }
}

// 32 blocks x 256 threads: 1 uint4 per thread, restore zeros, sum, ticket out.
__global__ __launch_bounds__(256)
void reduce_kernel(float* __restrict__ out) {
    __shared__ float sw[8];
    const int t = blockIdx.x * 256 + threadIdx.x;     // 0..8191

    uint4* p = reinterpret_cast<uint4*>(g_key) + t;
    const uint4 k = *p;
    *p = make_uint4(0u, 0u, 0u, 0u);                  // restore identity

    float sum = __uint_as_float(~k.x) + __uint_as_float(~k.y)
              + __uint_as_float(~k.z) + __uint_as_float(~k.w);

    #pragma unroll
    for (int o = 16; o; o >>= 1)
        sum += __shfl_xor_sync(0xffffffffu, sum, o);
    if ((threadIdx.x & 31) == 0) sw[threadIdx.x >> 5] = sum;
    __syncthreads();

    if (threadIdx.x == 0) {
        float v = 0.0f;
        #pragma unroll
        for (int w = 0; w < 8; w++) v += sw[w];
        atomicAdd(&g_acc, v);
        __threadfence();
        const unsigned ticket = atomicAdd(&g_cnt, 1u);
        if (ticket == 31u) {
            const float total = atomicAdd(&g_acc, 0.0f);  // coherent read
            out[0] = total * (1.0f / ((float)BATCH * (float)NPTS));
            __threadfence();
            g_acc = 0.0f;
            g_cnt = 0u;
        }
    }
}

extern "C" void kernel_launch(void* const* d_in, const int* in_sizes, int n_in,
                              void* d_out, int out_size) {
    const float* pred = (const float*)d_in[0];
    const float* gt   = (const float*)d_in[1];
    float* out = (float*)d_out;
    (void)in_sizes; (void)n_in; (void)out_size;

    dim3 grid(NCGRP, NRGRP, BATCH);   // 32 x 8 x 4 = 1024 blocks
    chamfer_main<<<grid, THREADS>>>(pred, gt);
    reduce_kernel<<<NKEY / 4 / 256, 256>>>(out);
}